// round 10
// baseline (speedup 1.0000x reference)
#include <cuda_runtime.h>
#include <cstdint>

#define NN 50000
#define NE 600000
#define DD 128
#define NL 4
#define NG 512
#define NC 10
#define AST 132        // padded smem stride (floats)
#define MT 64          // GEMM M tile
#define NTILES ((NN + MT - 1) / MT)   // 782
#define GGRID 148      // persistent CTAs

// ---- scratch (device globals: allocation-free) ----
__device__ float g_H[NN * DD];
__device__ float g_Z[NN * DD];
__device__ float g_T[NN * DD];
__device__ float g_sum[NL * DD];
__device__ float g_sqs[NL * DD];
__device__ float g_pool[NG * NL * DD];
__device__ uint32_t g_Wt[2][NL][DD * AST];   // transposed, padded, tf32-converted

__device__ int g_src[NE];
__device__ int g_dst[NE];
__device__ int g_batch[NN];
__device__ int g_deg[NN];
__device__ int g_ptr[NN + 1];
__device__ int g_off[NN];
__device__ int g_csr_src[NE];
__device__ int g_mode_ei;
__device__ int g_mode_b;

__device__ __forceinline__ void red_add_v4(float* p, float4 v) {
    asm volatile("red.global.add.v4.f32 [%0], {%1, %2, %3, %4};"
                 :: "l"(p), "f"(v.x), "f"(v.y), "f"(v.z), "f"(v.w)
                 : "memory");
}
__device__ __forceinline__ uint32_t f2tf32(float f) {
    uint32_t u;
    asm("cvt.rna.tf32.f32 %0, %1;" : "=r"(u) : "f"(f));
    return u;
}
__device__ __forceinline__ void mma_tf32(float& c0, float& c1, float& c2, float& c3,
                                         uint32_t a0, uint32_t a1, uint32_t a2, uint32_t a3,
                                         uint32_t b0, uint32_t b1) {
    asm volatile(
        "mma.sync.aligned.m16n8k8.row.col.f32.tf32.tf32.f32 "
        "{%0,%1,%2,%3}, {%4,%5,%6,%7}, {%8,%9}, {%0,%1,%2,%3};"
        : "+f"(c0), "+f"(c1), "+f"(c2), "+f"(c3)
        : "r"(a0), "r"(a1), "r"(a2), "r"(a3), "r"(b0), "r"(b1));
}

// ---------------- preamble ----------------
__global__ void detect_kernel(const int* __restrict__ ei32,
                              const int* __restrict__ b32) {
    int i = blockIdx.x * blockDim.x + threadIdx.x;
    int idx = 2 * i + 1;
    if (idx < 2 * NE) { if (ei32[idx] != 0) atomicExch(&g_mode_ei, 0); }
    if (idx < NN)     { if (b32[idx]  != 0) atomicExch(&g_mode_b, 0); }
}

// convert dtypes + histogram of dst degrees in one pass
__global__ void convert_hist_kernel(const int* __restrict__ ei32,
                                    const int* __restrict__ b32) {
    int i = blockIdx.x * blockDim.x + threadIdx.x;
    int m_ei = g_mode_ei, m_b = g_mode_b;
    if (i < NE) {
        int s = m_ei ? ei32[2 * i]        : ei32[i];
        int d = m_ei ? ei32[2 * (NE + i)] : ei32[NE + i];
        g_src[i] = s;
        g_dst[i] = d;
        atomicAdd(&g_deg[d], 1);
    }
    if (i < NN) g_batch[i] = m_b ? b32[2 * i] : b32[i];
}

// block 0: exclusive scan of degrees; blocks 1..128: weight transpose/tf32 prep
__global__ void scan_wprep_kernel(const float* __restrict__ W1,
                                  const float* __restrict__ W2) {
    if (blockIdx.x == 0) {
        __shared__ int sh[1024];
        int t = threadIdx.x;
        const int CH = (NN + 1023) / 1024;
        int b0 = t * CH, b1 = min(b0 + CH, NN);
        int s = 0;
        for (int i = b0; i < b1; i++) s += g_deg[i];
        sh[t] = s;
        __syncthreads();
        for (int off = 1; off < 1024; off <<= 1) {
            int v = (t >= off) ? sh[t - off] : 0;
            __syncthreads();
            sh[t] += v;
            __syncthreads();
        }
        int run = (t > 0) ? sh[t - 1] : 0;
        for (int i = b0; i < b1; i++) {
            g_ptr[i] = run; g_off[i] = run;
            run += g_deg[i];
        }
        if (t == 0) g_ptr[NN] = NE;
    } else {
        int i = (blockIdx.x - 1) * 1024 + threadIdx.x;   // over 2*NL*DD*DD = 131072
        if (i < 2 * NL * DD * DD) {
            int which = i / (NL * DD * DD);
            int r = i % (NL * DD * DD);
            int l = r / (DD * DD);
            int e = r % (DD * DD);
            int k = e / DD, n = e % DD;
            const float* w = which ? W2 : W1;
            g_Wt[which][l][n * AST + k] = f2tf32(w[l * DD * DD + k * DD + n]);
        }
    }
}

__global__ void scatter_kernel() {
    int i = blockIdx.x * blockDim.x + threadIdx.x;
    if (i >= NE) return;
    int d = g_dst[i];
    int pos = atomicAdd(&g_off[d], 1);
    g_csr_src[pos] = g_src[i];
}

// ---------------- fused (1+eps)*h + CSR neighbor-sum ----------------
__global__ void agg_kernel(const float* __restrict__ x,
                           const float* __restrict__ eps, int l) {
    int warp = (blockIdx.x * blockDim.x + threadIdx.x) >> 5;
    if (warp >= NN) return;
    int lane = threadIdx.x & 31;
    const float* h = l ? g_H : x;
    const float4* hv = (const float4*)h;
    float e = 1.0f + __ldg(&eps[l]);
    float4 a = hv[warp * 32 + lane];
    float4 acc = make_float4(a.x * e, a.y * e, a.z * e, a.w * e);
    int p = __ldg(&g_ptr[warp]);
    int p1 = __ldg(&g_ptr[warp + 1]);
    for (; p + 4 <= p1; p += 4) {
        int s0 = __ldg(&g_csr_src[p]);
        int s1 = __ldg(&g_csr_src[p + 1]);
        int s2 = __ldg(&g_csr_src[p + 2]);
        int s3 = __ldg(&g_csr_src[p + 3]);
        float4 v0 = __ldg(&hv[s0 * 32 + lane]);
        float4 v1 = __ldg(&hv[s1 * 32 + lane]);
        float4 v2 = __ldg(&hv[s2 * 32 + lane]);
        float4 v3 = __ldg(&hv[s3 * 32 + lane]);
        acc.x += v0.x + v1.x + v2.x + v3.x;
        acc.y += v0.y + v1.y + v2.y + v3.y;
        acc.z += v0.z + v1.z + v2.z + v3.z;
        acc.w += v0.w + v1.w + v2.w + v3.w;
    }
    for (; p < p1; p++) {
        int s = __ldg(&g_csr_src[p]);
        float4 v = __ldg(&hv[s * 32 + lane]);
        acc.x += v.x; acc.y += v.y; acc.z += v.z; acc.w += v.w;
    }
    ((float4*)g_Z)[warp * 32 + lane] = acc;
}

// ---------------- persistent mma.sync tf32 GEMM ----------------
// grid=148, 512 threads (16 warps: 4 along M x 4 along N; warp tile 16x32).
// B resident in smem for whole launch; A double-buffered via register prefetch.
#define SMEMP ((DD * AST + 2 * MT * AST) * 4)

__device__ __forceinline__ void load_a_regs(const float* __restrict__ Ain,
                                            int tile, int tid, float4* pf) {
    int row0 = tile * MT;
    #pragma unroll
    for (int u = 0; u < 4; u++) {
        int j = tid + u * 512;         // < MT*32 = 2048
        int m = j >> 5, k4 = j & 31;
        int gm = row0 + m;
        pf[u] = (gm < NN) ? __ldg(&((const float4*)(Ain + (size_t)gm * DD))[k4])
                          : make_float4(0.f, 0.f, 0.f, 0.f);
    }
}
__device__ __forceinline__ void store_a_smem(uint32_t* As, int tid, const float4* pf) {
    #pragma unroll
    for (int u = 0; u < 4; u++) {
        int j = tid + u * 512;
        int m = j >> 5, k4 = j & 31;
        uint32_t* p = &As[m * AST + k4 * 4];
        p[0] = f2tf32(pf[u].x); p[1] = f2tf32(pf[u].y);
        p[2] = f2tf32(pf[u].z); p[3] = f2tf32(pf[u].w);
    }
}

template<bool RELU, bool STATS>
__global__ __launch_bounds__(512, 1)
void gemm_persist_kernel(const uint32_t* __restrict__ Wt,
                         const float* __restrict__ bias,
                         const float* __restrict__ Ain,
                         float* __restrict__ Cout,
                         int l) {
    extern __shared__ __align__(16) uint32_t smem[];
    uint32_t* Bs = smem;                        // [128][AST] n-major
    uint32_t* As[2] = { smem + DD * AST, smem + DD * AST + MT * AST };
    int tid = threadIdx.x;
    int wid = tid >> 5, lane = tid & 31;
    int wm = (wid & 3) * 16;
    int wn = (wid >> 2) * 32;
    int grp = lane >> 2, qid = lane & 3;

    // B: load once (already tf32 bits, padded)
    #pragma unroll 4
    for (int i = tid; i < DD * AST / 4; i += 512)
        ((uint4*)Bs)[i] = ((const uint4*)Wt)[i];

    // bias fragments fixed per warp across all tiles
    float bv[4][2];
    #pragma unroll
    for (int nt = 0; nt < 4; nt++) {
        int col = wn + nt * 8 + 2 * qid;
        bv[nt][0] = __ldg(&bias[col]);
        bv[nt][1] = __ldg(&bias[col + 1]);
    }

    int tile = blockIdx.x;
    float4 pf[4];
    load_a_regs(Ain, tile, tid, pf);
    store_a_smem(As[0], tid, pf);
    __syncthreads();

    int buf = 0;
    for (; tile < NTILES; tile += GGRID) {
        int nxt = tile + GGRID;
        if (nxt < NTILES) load_a_regs(Ain, nxt, tid, pf);

        const uint32_t* A0 = As[buf];
        float acc[4][4];
        #pragma unroll
        for (int j = 0; j < 4; j++)
            #pragma unroll
            for (int q = 0; q < 4; q++) acc[j][q] = 0.f;

        #pragma unroll
        for (int ks = 0; ks < 16; ks++) {
            int k0 = ks * 8;
            uint32_t a0 = A0[(wm + grp) * AST + k0 + qid];
            uint32_t a1 = A0[(wm + grp + 8) * AST + k0 + qid];
            uint32_t a2 = A0[(wm + grp) * AST + k0 + qid + 4];
            uint32_t a3 = A0[(wm + grp + 8) * AST + k0 + qid + 4];
            #pragma unroll
            for (int nt = 0; nt < 4; nt++) {
                uint32_t b0 = Bs[(wn + nt * 8 + grp) * AST + k0 + qid];
                uint32_t b1 = Bs[(wn + nt * 8 + grp) * AST + k0 + qid + 4];
                mma_tf32(acc[nt][0], acc[nt][1], acc[nt][2], acc[nt][3],
                         a0, a1, a2, a3, b0, b1);
            }
        }

        // epilogue for this tile
        int row0 = tile * MT;
        int r = row0 + wm + grp;
        #pragma unroll
        for (int nt = 0; nt < 4; nt++) {
            int col = wn + nt * 8 + 2 * qid;
            float v0 = acc[nt][0] + bv[nt][0];
            float v1 = acc[nt][1] + bv[nt][1];
            float v2 = acc[nt][2] + bv[nt][0];
            float v3 = acc[nt][3] + bv[nt][1];
            if (RELU) {
                v0 = fmaxf(v0, 0.f); v1 = fmaxf(v1, 0.f);
                v2 = fmaxf(v2, 0.f); v3 = fmaxf(v3, 0.f);
            }
            float s0 = 0.f, s1 = 0.f, q0 = 0.f, q1 = 0.f;
            if (r < NN) {
                *(float2*)(Cout + (size_t)r * DD + col) = make_float2(v0, v1);
                if (STATS) { s0 += v0; s1 += v1; q0 += v0 * v0; q1 += v1 * v1; }
            }
            if (r + 8 < NN) {
                *(float2*)(Cout + (size_t)(r + 8) * DD + col) = make_float2(v2, v3);
                if (STATS) { s0 += v2; s1 += v3; q0 += v2 * v2; q1 += v3 * v3; }
            }
            if (STATS) {
                #pragma unroll
                for (int m = 4; m < 32; m <<= 1) {
                    s0 += __shfl_xor_sync(0xFFFFFFFF, s0, m);
                    s1 += __shfl_xor_sync(0xFFFFFFFF, s1, m);
                    q0 += __shfl_xor_sync(0xFFFFFFFF, q0, m);
                    q1 += __shfl_xor_sync(0xFFFFFFFF, q1, m);
                }
                if (grp == 0) {
                    atomicAdd(&g_sum[l * DD + col], s0);
                    atomicAdd(&g_sum[l * DD + col + 1], s1);
                    atomicAdd(&g_sqs[l * DD + col], q0);
                    atomicAdd(&g_sqs[l * DD + col + 1], q1);
                }
            }
        }

        if (nxt < NTILES) store_a_smem(As[buf ^ 1], tid, pf);
        __syncthreads();
        buf ^= 1;
    }
}

// ---------------- BN finalize + relu + pool (fused) ----------------
__global__ void bn_relu_pool_kernel(const float* __restrict__ gamma,
                                    const float* __restrict__ beta, int l) {
    __shared__ float s_sc[DD], s_sf[DD];
    int tid = threadIdx.x;
    if (tid < DD) {
        float mean = g_sum[l * DD + tid] * (1.0f / NN);
        float var = g_sqs[l * DD + tid] * (1.0f / NN) - mean * mean;
        float sc = __ldg(&gamma[l * DD + tid]) * rsqrtf(var + 1e-5f);
        s_sc[tid] = sc;
        s_sf[tid] = __ldg(&beta[l * DD + tid]) - mean * sc;
    }
    __syncthreads();
    int i = blockIdx.x * blockDim.x + tid;
    if (i >= NN * DD / 4) return;
    int r = i >> 5;
    int c4 = (i & 31) << 2;
    float4 z = ((const float4*)g_Z)[i];
    float4 hv;
    hv.x = fmaxf(z.x * s_sc[c4]     + s_sf[c4],     0.f);
    hv.y = fmaxf(z.y * s_sc[c4 + 1] + s_sf[c4 + 1], 0.f);
    hv.z = fmaxf(z.z * s_sc[c4 + 2] + s_sf[c4 + 2], 0.f);
    hv.w = fmaxf(z.w * s_sc[c4 + 3] + s_sf[c4 + 3], 0.f);
    ((float4*)g_H)[i] = hv;
    int b = __ldg(&g_batch[r]);
    red_add_v4(&g_pool[(size_t)b * (NL * DD) + l * DD + c4], hv);
}

// ---------------- final linear ----------------
__global__ void final_kernel(const float* __restrict__ Wlin,
                             const float* __restrict__ blin,
                             float* __restrict__ out) {
    int t = blockIdx.x * blockDim.x + threadIdx.x;
    if (t >= NG * NC) return;
    int gph = t / NC, c = t % NC;
    float acc = __ldg(&blin[c]);
    const float* prow = &g_pool[(size_t)gph * (NL * DD)];
    #pragma unroll 8
    for (int k = 0; k < NL * DD; k++)
        acc += __ldg(&prow[k]) * __ldg(&Wlin[k * NC + c]);
    out[gph * NC + c] = acc;
}

extern "C" void kernel_launch(void* const* d_in, const int* in_sizes, int n_in,
                              void* d_out, int out_size) {
    const float* x     = (const float*)d_in[0];
    const int*   ei32  = (const int*)d_in[1];
    const int*   b32   = (const int*)d_in[2];
    const float* W1    = (const float*)d_in[3];
    const float* b1    = (const float*)d_in[4];
    const float* W2    = (const float*)d_in[5];
    const float* b2    = (const float*)d_in[6];
    const float* eps   = (const float*)d_in[7];
    const float* gamma = (const float*)d_in[8];
    const float* beta  = (const float*)d_in[9];
    const float* Wlin  = (const float*)d_in[10];
    const float* blin  = (const float*)d_in[11];
    float* out = (float*)d_out;

    cudaFuncSetAttribute(gemm_persist_kernel<true, false>,
                         cudaFuncAttributeMaxDynamicSharedMemorySize, SMEMP);
    cudaFuncSetAttribute(gemm_persist_kernel<false, true>,
                         cudaFuncAttributeMaxDynamicSharedMemorySize, SMEMP);

    // zero / init via memset nodes (not kernel launches)
    void *p_mode_ei, *p_mode_b, *p_deg, *p_pool, *p_sum, *p_sqs;
    cudaGetSymbolAddress(&p_mode_ei, g_mode_ei);
    cudaGetSymbolAddress(&p_mode_b,  g_mode_b);
    cudaGetSymbolAddress(&p_deg,     g_deg);
    cudaGetSymbolAddress(&p_pool,    g_pool);
    cudaGetSymbolAddress(&p_sum,     g_sum);
    cudaGetSymbolAddress(&p_sqs,     g_sqs);
    cudaMemsetAsync(p_mode_ei, 1, 4);              // 0x01010101 != 0
    cudaMemsetAsync(p_mode_b,  1, 4);
    cudaMemsetAsync(p_deg,  0, NN * sizeof(int));
    cudaMemsetAsync(p_pool, 0, NG * NL * DD * sizeof(float));
    cudaMemsetAsync(p_sum,  0, NL * DD * sizeof(float));
    cudaMemsetAsync(p_sqs,  0, NL * DD * sizeof(float));

    detect_kernel<<<(NE + 255) / 256, 256>>>(ei32, b32);            // launch 0
    convert_hist_kernel<<<(NE + 255) / 256, 256>>>(ei32, b32);      // launch 1
    scan_wprep_kernel<<<129, 1024>>>(W1, W2);                       // launch 2
    scatter_kernel<<<(NE + 255) / 256, 256>>>();                    // launch 3

    int zgrid = (NN * DD / 4 + 255) / 256;
    int agrid = (NN * 32 + 255) / 256;

    uint32_t* wt_base;
    cudaGetSymbolAddress((void**)&wt_base, g_Wt);
    float *zb, *tb;
    cudaGetSymbolAddress((void**)&zb, g_Z);
    cudaGetSymbolAddress((void**)&tb, g_T);

    for (int l = 0; l < NL; l++) {
        agg_kernel<<<agrid, 256>>>(x, eps, l);                      // launch 4 (l=0)
        gemm_persist_kernel<true, false><<<GGRID, 512, SMEMP>>>(
            wt_base + (size_t)l * DD * AST, b1 + l * DD, zb, tb, l);      // launch 5 -> ncu
        gemm_persist_kernel<false, true><<<GGRID, 512, SMEMP>>>(
            wt_base + (size_t)(NL + l) * DD * AST, b2 + l * DD, tb, zb, l);
        bn_relu_pool_kernel<<<zgrid, 256>>>(gamma, beta, l);
    }
    final_kernel<<<(NG * NC + 255) / 256, 256>>>(Wlin, blin, out);
}